// round 1
// baseline (speedup 1.0000x reference)
#include <cuda_runtime.h>
#include <math.h>
#include <stdint.h>

// ---------------- problem dims ----------------
constexpr int B_   = 16;
constexpr int NQ   = 32;
constexpr int NN   = 128;
constexpr int T_   = 352;
constexpr int D_   = 768;
constexpr int H_   = 8;
constexpr int NLAY = 6;
constexpr int FF   = 3072;
constexpr int L_   = NQ + NN + T_;   // 512
constexpr int TS   = NQ + NN;        // 160 (text start)
constexpr int HD   = D_ / H_;        // 96
constexpr float NEGB = -1e9f;

// ---------------- device scratch (allocation-free rule: module globals) ----
__device__ float g_x  [B_ * L_ * D_];      // activations [B*L, D]
__device__ float g_tmp[B_ * L_ * D_];      // pre-LN buffer
__device__ float g_ctx[B_ * L_ * D_];      // attention context
__device__ float g_qkv[B_ * L_ * 3 * D_];  // fused qkv
__device__ float g_ff [B_ * L_ * FF];      // ffn hidden

// ============================================================================
// Generic 128x128x8 register-tiled SGEMM, row-major A[M,K] @ B[K,N] + epilogue
// EPI: 0 = +bias       1 = +bias +residual       2 = gelu(+bias)
// mapGraph != 0 : output row r -> (r/NN)*L_ + NQ + (r%NN)   (graph scatter)
// ============================================================================
template <int EPI>
__global__ __launch_bounds__(256)
void sgemm128(const float* __restrict__ A, const float* __restrict__ Bm,
              const float* __restrict__ bias, const float* __restrict__ resid,
              float* __restrict__ C, int M, int N, int K, int mapGraph)
{
    __shared__ float As[8][128];
    __shared__ float Bs[8][128];

    const int tid = threadIdx.x;
    const int br = blockIdx.y, bc = blockIdx.x;

    const int arow = tid >> 1, acol = (tid & 1) * 4;
    const int brow = tid >> 5, bcol = (tid & 31) * 4;

    const float* Ap = A + (size_t)(br * 128 + arow) * K + acol;
    const float* Bp = Bm + (size_t)brow * N + bc * 128 + bcol;

    const int tx = tid & 15, ty = tid >> 4;

    float acc[8][8];
#pragma unroll
    for (int i = 0; i < 8; i++)
#pragma unroll
        for (int j = 0; j < 8; j++) acc[i][j] = 0.f;

    for (int kt = 0; kt < K; kt += 8) {
        float4 av = *(const float4*)(Ap + kt);
        As[acol + 0][arow] = av.x;
        As[acol + 1][arow] = av.y;
        As[acol + 2][arow] = av.z;
        As[acol + 3][arow] = av.w;
        *(float4*)&Bs[brow][bcol] = *(const float4*)(Bp + (size_t)kt * N);
        __syncthreads();

#pragma unroll
        for (int k = 0; k < 8; k++) {
            float a[8], b[8];
            *(float4*)(a)     = *(float4*)&As[k][ty * 8];
            *(float4*)(a + 4) = *(float4*)&As[k][ty * 8 + 4];
            *(float4*)(b)     = *(float4*)&Bs[k][tx * 8];
            *(float4*)(b + 4) = *(float4*)&Bs[k][tx * 8 + 4];
#pragma unroll
            for (int i = 0; i < 8; i++)
#pragma unroll
                for (int j = 0; j < 8; j++)
                    acc[i][j] += a[i] * b[j];
        }
        __syncthreads();
    }

#pragma unroll
    for (int i = 0; i < 8; i++) {
        int row = br * 128 + ty * 8 + i;
        int orow = mapGraph ? (row / NN) * L_ + NQ + (row % NN) : row;
#pragma unroll
        for (int j = 0; j < 8; j++) {
            int col = bc * 128 + tx * 8 + j;
            float v = acc[i][j] + bias[col];
            if (EPI == 1) v += resid[(size_t)row * N + col];
            if (EPI == 2) v = 0.5f * v * (1.0f + erff(v * 0.7071067811865475f));
            C[(size_t)orow * N + col] = v;
        }
    }
}

// ============================================================================
// Row LayerNorm (D=768), 256 threads/row. If pos != null, adds pos+tok first
// (embedding path). Two-pass mean/var to match reference closely.
// ============================================================================
__global__ __launch_bounds__(256)
void ln_kernel(const float* __restrict__ in, float* __restrict__ out,
               const float* __restrict__ g, const float* __restrict__ bta,
               const float* __restrict__ pos, const float* __restrict__ tok)
{
    const int row = blockIdx.x;          // b*L + l
    const int l = row % L_;
    const int tid = threadIdx.x;
    const float* ip = in + (size_t)row * D_;

    float v[3];
    float s = 0.f;
#pragma unroll
    for (int i = 0; i < 3; i++) {
        int d = tid + i * 256;
        float x = ip[d];
        if (pos) x += pos[l * D_ + d] + tok[d];
        v[i] = x;
        s += x;
    }
    __shared__ float red[256];
    red[tid] = s;
    __syncthreads();
    for (int o = 128; o > 0; o >>= 1) {
        if (tid < o) red[tid] += red[tid + o];
        __syncthreads();
    }
    float mean = red[0] * (1.0f / 768.0f);
    __syncthreads();

    float ss = 0.f;
#pragma unroll
    for (int i = 0; i < 3; i++) {
        float d0 = v[i] - mean;
        ss += d0 * d0;
    }
    red[tid] = ss;
    __syncthreads();
    for (int o = 128; o > 0; o >>= 1) {
        if (tid < o) red[tid] += red[tid + o];
        __syncthreads();
    }
    float inv = rsqrtf(red[0] * (1.0f / 768.0f) + 1e-12f);

    float* op = out + (size_t)row * D_;
#pragma unroll
    for (int i = 0; i < 3; i++) {
        int d = tid + i * 256;
        op[d] = (v[i] - mean) * inv * g[d] + bta[d];
    }
}

// ============================================================================
// Fused attention: one block per (b*H + h, q-tile of 64). Full 512-wide score
// row held in smem; 2-pass softmax; masked with the ITG prefix-LM mask.
// qkv layout: row (b*L + l), 2304 cols = [q | k | v], head h at offset h*96.
// ============================================================================
constexpr int SW = 513;                   // S row stride (conflict-free)
constexpr int VW = 100;                   // V row stride
constexpr int ATTN_SMEM =
    (96 * 64 * 2 + 64 * VW + 64 * SW) * 4 + L_ * 4;

__global__ __launch_bounds__(256)
void attn_kernel(const float* __restrict__ qkv, float* __restrict__ ctx,
                 const int* __restrict__ text_atts, const int* __restrict__ graph_mask)
{
    const int bh = blockIdx.x;
    const int b = bh / H_, h = bh % H_;
    const int qt = blockIdx.y;            // 0..7
    const int tid = threadIdx.x;

    extern __shared__ float sm[];
    float* Qs = sm;                        // [96][64] transposed
    float* Ks = Qs + 96 * 64;              // [96][64] transposed
    float* Vs = Ks + 96 * 64;              // [64][VW] row-major
    float* S  = Vs + 64 * VW;              // [64][SW]
    int*   keep = (int*)(S + 64 * SW);     // [512]

    // ---- build keep[] for this batch ----
    for (int j = tid; j < L_; j += 256)
        keep[j] = (j < NQ) ? 1
                : (j < TS) ? graph_mask[b * NN + (j - NQ)]
                           : text_atts[b * T_ + (j - TS)];

    // ---- load Q tile (transposed) ----
    const float* qbase = qkv + (size_t)(b * L_ + qt * 64) * (3 * D_) + h * HD;
    for (int e = tid; e < 64 * 24; e += 256) {
        int r = e / 24, c4 = (e % 24) * 4;
        float4 v = *(const float4*)(qbase + (size_t)r * (3 * D_) + c4);
        Qs[(c4 + 0) * 64 + r] = v.x;
        Qs[(c4 + 1) * 64 + r] = v.y;
        Qs[(c4 + 2) * 64 + r] = v.z;
        Qs[(c4 + 3) * 64 + r] = v.w;
    }
    __syncthreads();

    const int tx = tid & 15, ty = tid >> 4;
    const float scale = 0.10206207261596577f;  // 1/sqrt(96)

    // ---- scores: 8 chunks of 64 keys ----
    for (int kc = 0; kc < 8; kc++) {
        const float* kb = qkv + (size_t)(b * L_ + kc * 64) * (3 * D_) + D_ + h * HD;
        for (int e = tid; e < 64 * 24; e += 256) {
            int r = e / 24, c4 = (e % 24) * 4;
            float4 v = *(const float4*)(kb + (size_t)r * (3 * D_) + c4);
            Ks[(c4 + 0) * 64 + r] = v.x;
            Ks[(c4 + 1) * 64 + r] = v.y;
            Ks[(c4 + 2) * 64 + r] = v.z;
            Ks[(c4 + 3) * 64 + r] = v.w;
        }
        __syncthreads();

        float acc[4][4];
#pragma unroll
        for (int i = 0; i < 4; i++)
#pragma unroll
            for (int j = 0; j < 4; j++) acc[i][j] = 0.f;

#pragma unroll 4
        for (int d = 0; d < 96; d++) {
            float a[4], bb[4];
#pragma unroll
            for (int i = 0; i < 4; i++) a[i]  = Qs[d * 64 + ty * 4 + i];
#pragma unroll
            for (int j = 0; j < 4; j++) bb[j] = Ks[d * 64 + tx * 4 + j];
#pragma unroll
            for (int i = 0; i < 4; i++)
#pragma unroll
                for (int j = 0; j < 4; j++) acc[i][j] += a[i] * bb[j];
        }

#pragma unroll
        for (int i = 0; i < 4; i++) {
            int qg = qt * 64 + ty * 4 + i;
            int kq = keep[qg];
#pragma unroll
            for (int j = 0; j < 4; j++) {
                int kg = kc * 64 + tx * 4 + j;
                bool ok = (kq != 0) && (keep[kg] != 0);
                if (qg < TS) {               // prefix query cannot see text
                    if (kg >= TS) ok = false;
                } else if (kg >= TS) {       // text-text: causal
                    if (qg < kg) ok = false;
                }
                S[(ty * 4 + i) * SW + kg] = acc[i][j] * scale + (ok ? 0.f : NEGB);
            }
        }
        __syncthreads();
    }

    // ---- softmax, one thread per row ----
    if (tid < 64) {
        float* row = S + tid * SW;
        float m = -INFINITY;
        for (int k = 0; k < L_; k++) m = fmaxf(m, row[k]);
        float sum = 0.f;
        for (int k = 0; k < L_; k++) {
            float e = __expf(row[k] - m);
            row[k] = e;
            sum += e;
        }
        float inv = 1.f / sum;
        for (int k = 0; k < L_; k++) row[k] *= inv;
    }
    __syncthreads();

    // ---- P @ V ----
    float o[4][6];
#pragma unroll
    for (int i = 0; i < 4; i++)
#pragma unroll
        for (int j = 0; j < 6; j++) o[i][j] = 0.f;

    for (int kc = 0; kc < 8; kc++) {
        const float* vb = qkv + (size_t)(b * L_ + kc * 64) * (3 * D_) + 2 * D_ + h * HD;
        for (int e = tid; e < 64 * 24; e += 256) {
            int r = e / 24, c4 = (e % 24) * 4;
            float4 v = *(const float4*)(vb + (size_t)r * (3 * D_) + c4);
            *(float4*)&Vs[r * VW + c4] = v;
        }
        __syncthreads();

#pragma unroll 2
        for (int ki = 0; ki < 64; ki++) {
            float a[4], bb[6];
#pragma unroll
            for (int i = 0; i < 4; i++) a[i] = S[(ty * 4 + i) * SW + kc * 64 + ki];
#pragma unroll
            for (int j = 0; j < 6; j++) bb[j] = Vs[ki * VW + tx * 6 + j];
#pragma unroll
            for (int i = 0; i < 4; i++)
#pragma unroll
                for (int j = 0; j < 6; j++) o[i][j] += a[i] * bb[j];
        }
        __syncthreads();
    }

#pragma unroll
    for (int i = 0; i < 4; i++) {
        float* op = ctx + (size_t)(b * L_ + qt * 64 + ty * 4 + i) * D_ + h * HD + tx * 6;
#pragma unroll
        for (int j = 0; j < 6; j++) op[j] = o[i][j];
    }
}

// ============================================================================
// misc elementwise
// ============================================================================
__global__ void fill_embed(const float* __restrict__ qtok,
                           const float* __restrict__ temb,
                           float* __restrict__ out)
{
    int idx = blockIdx.x * blockDim.x + threadIdx.x;
    if (idx >= B_ * L_ * D_) return;
    int rem = idx % (L_ * D_);
    int b = idx / (L_ * D_);
    int l = rem / D_, d = rem % D_;
    if (l < NQ)
        out[idx] = qtok[l * D_ + d];
    else if (l >= TS)
        out[idx] = temb[(size_t)(b * T_ + (l - TS)) * D_ + d];
    // graph rows written by gproj GEMM
}

__global__ void copy_out(const float* __restrict__ x, float* __restrict__ out, int n)
{
    int idx = blockIdx.x * blockDim.x + threadIdx.x;
    if (idx >= n) return;
    int rem = idx % (T_ * D_);
    int b = idx / (T_ * D_);
    int t = rem / D_, d = rem % D_;
    out[idx] = x[(size_t)(b * L_ + TS + t) * D_ + d];
}

// ============================================================================
// launcher
// ============================================================================
extern "C" void kernel_launch(void* const* d_in, const int* in_sizes, int n_in,
                              void* d_out, int out_size)
{
    const float* gnf     = (const float*)d_in[0];
    const float* temb    = (const float*)d_in[1];
    const int*   tatt    = (const int*)  d_in[2];
    const int*   gmask   = (const int*)  d_in[3];
    const float* qtok    = (const float*)d_in[4];
    const float* gproj_w = (const float*)d_in[5];
    const float* gproj_b = (const float*)d_in[6];
    const float* pos     = (const float*)d_in[7];
    const float* tok     = (const float*)d_in[8];
    const float* elng    = (const float*)d_in[9];
    const float* elnb    = (const float*)d_in[10];
    const float* qkvw    = (const float*)d_in[11];
    const float* qkvb    = (const float*)d_in[12];
    const float* aow     = (const float*)d_in[13];
    const float* aob     = (const float*)d_in[14];
    const float* ln1g    = (const float*)d_in[15];
    const float* ln1b    = (const float*)d_in[16];
    const float* ff1w    = (const float*)d_in[17];
    const float* ff1b    = (const float*)d_in[18];
    const float* ff2w    = (const float*)d_in[19];
    const float* ff2b    = (const float*)d_in[20];
    const float* ln2g    = (const float*)d_in[21];
    const float* ln2b    = (const float*)d_in[22];

    float *px, *ptmp, *pctx, *pqkv, *pff;
    cudaGetSymbolAddress((void**)&px,   g_x);
    cudaGetSymbolAddress((void**)&ptmp, g_tmp);
    cudaGetSymbolAddress((void**)&pctx, g_ctx);
    cudaGetSymbolAddress((void**)&pqkv, g_qkv);
    cudaGetSymbolAddress((void**)&pff,  g_ff);

    cudaFuncSetAttribute(attn_kernel, cudaFuncAttributeMaxDynamicSharedMemorySize,
                         ATTN_SMEM);

    const int NROWS = B_ * L_;   // 8192

    // ---- embeddings ----
    fill_embed<<<(B_ * L_ * D_ + 255) / 256, 256>>>(qtok, temb, ptmp);
    sgemm128<0><<<dim3(D_ / 128, (B_ * NN) / 128), 256>>>(
        gnf, gproj_w, gproj_b, nullptr, ptmp, B_ * NN, D_, D_, 1);
    ln_kernel<<<NROWS, 256>>>(ptmp, px, elng, elnb, pos, tok);

    // ---- 6 encoder layers ----
    for (int i = 0; i < NLAY; i++) {
        sgemm128<0><<<dim3((3 * D_) / 128, NROWS / 128), 256>>>(
            px, qkvw + (size_t)i * D_ * 3 * D_, qkvb + (size_t)i * 3 * D_,
            nullptr, pqkv, NROWS, 3 * D_, D_, 0);

        attn_kernel<<<dim3(B_ * H_, L_ / 64), 256, ATTN_SMEM>>>(pqkv, pctx, tatt, gmask);

        sgemm128<1><<<dim3(D_ / 128, NROWS / 128), 256>>>(
            pctx, aow + (size_t)i * D_ * D_, aob + (size_t)i * D_,
            px, ptmp, NROWS, D_, D_, 0);
        ln_kernel<<<NROWS, 256>>>(ptmp, px, ln1g + (size_t)i * D_, ln1b + (size_t)i * D_,
                                  nullptr, nullptr);

        sgemm128<2><<<dim3(FF / 128, NROWS / 128), 256>>>(
            px, ff1w + (size_t)i * D_ * FF, ff1b + (size_t)i * FF,
            nullptr, pff, NROWS, FF, D_, 0);

        sgemm128<1><<<dim3(D_ / 128, NROWS / 128), 256>>>(
            pff, ff2w + (size_t)i * FF * D_, ff2b + (size_t)i * D_,
            px, ptmp, NROWS, D_, FF, 0);
        ln_kernel<<<NROWS, 256>>>(ptmp, px, ln2g + (size_t)i * D_, ln2b + (size_t)i * D_,
                                  nullptr, nullptr);
    }

    // ---- output: text rows ----
    copy_out<<<(out_size + 255) / 256, 256>>>(px, (float*)d_out, out_size);
}

// round 3
// speedup vs baseline: 2.0647x; 2.0647x over previous
#include <cuda_runtime.h>
#include <math.h>
#include <stdint.h>

// ---------------- problem dims ----------------
constexpr int B_   = 16;
constexpr int NQ   = 32;
constexpr int NN   = 128;
constexpr int T_   = 352;
constexpr int D_   = 768;
constexpr int H_   = 8;
constexpr int NLAY = 6;
constexpr int FF   = 3072;
constexpr int L_   = NQ + NN + T_;   // 512
constexpr int TS   = NQ + NN;        // 160 (text start)
constexpr int HD   = D_ / H_;        // 96
constexpr float NEGB = -1e9f;

// ---------------- device scratch ----------------
__device__ float g_x  [B_ * L_ * D_];
__device__ float g_tmp[B_ * L_ * D_];
__device__ float g_ctx[B_ * L_ * D_];
__device__ float g_qkv[B_ * L_ * 3 * D_];
__device__ float g_ff [B_ * L_ * FF];

// ============================================================================
// TF32 tensor-core GEMM: 128x128 block tile, 8 warps of 64x32, K-tile 16,
// double-buffered smem with register staging. mma.sync.m16n8k8 tf32.
// EPI: 0 = +bias   1 = +bias +residual   2 = gelu(+bias)
// mapGraph: output row r -> (r/NN)*L_ + NQ + (r%NN)
// ============================================================================
__device__ __forceinline__ uint32_t f2tf(float x) {
    uint32_t r;
    asm("cvt.rna.tf32.f32 %0, %1;" : "=r"(r) : "f"(x));
    return r;
}

__device__ __forceinline__ void mma_tf32(float c[4], const uint32_t a[4],
                                         const uint32_t b[2]) {
    asm volatile(
        "mma.sync.aligned.m16n8k8.row.col.f32.tf32.tf32.f32 "
        "{%0,%1,%2,%3}, {%4,%5,%6,%7}, {%8,%9}, {%0,%1,%2,%3};"
        : "+f"(c[0]), "+f"(c[1]), "+f"(c[2]), "+f"(c[3])
        : "r"(a[0]), "r"(a[1]), "r"(a[2]), "r"(a[3]), "r"(b[0]), "r"(b[1]));
}

constexpr int ASTR = 20;    // A smem row stride (floats) — bank-conflict-free
constexpr int BSTR = 136;   // B smem row stride (floats) — bank-conflict-free

template <int EPI>
__global__ __launch_bounds__(256)
void tgemm(const float* __restrict__ A, const float* __restrict__ Bm,
           const float* __restrict__ bias, const float* __restrict__ resid,
           float* __restrict__ C, int M, int N, int K, int mapGraph)
{
    __shared__ uint32_t As[2][128 * ASTR];
    __shared__ uint32_t Bs[2][16 * BSTR];

    const int tid  = threadIdx.x;
    const int br   = blockIdx.y, bc = blockIdx.x;
    const int lane = tid & 31,  wid = tid >> 5;
    const int wm = (wid >> 2) * 64;      // warp row base (0 or 64)
    const int wn = (wid & 3) * 32;       // warp col base (0,32,64,96)
    const int lq = lane >> 2;            // 0..7
    const int lr = lane & 3;             // 0..3

    float acc[4][4][4];
#pragma unroll
    for (int mt = 0; mt < 4; mt++)
#pragma unroll
        for (int nt = 0; nt < 4; nt++)
#pragma unroll
            for (int r = 0; r < 4; r++) acc[mt][nt][r] = 0.f;

    const int nkt = K >> 4;

    float4 pa[2], pb[2];

    // ---- tile load helpers (by index math; 2 float4 each for A and B) ----
    auto ldA = [&](int kt) {
#pragma unroll
        for (int i = 0; i < 2; i++) {
            int id  = tid + i * 256;           // 0..511
            int row = id >> 2, cg = (id & 3) << 2;
            pa[i] = *(const float4*)(A + (size_t)(br * 128 + row) * K + kt * 16 + cg);
        }
    };
    auto ldB = [&](int kt) {
#pragma unroll
        for (int i = 0; i < 2; i++) {
            int id  = tid + i * 256;
            int row = id >> 5, cg = (id & 31) << 2;
            pb[i] = *(const float4*)(Bm + (size_t)(kt * 16 + row) * N + bc * 128 + cg);
        }
    };
    auto stAB = [&](int buf) {
#pragma unroll
        for (int i = 0; i < 2; i++) {
            int id  = tid + i * 256;
            int row = id >> 2, cg = (id & 3) << 2;
            uint32_t* p = &As[buf][row * ASTR + cg];
            p[0] = f2tf(pa[i].x); p[1] = f2tf(pa[i].y);
            p[2] = f2tf(pa[i].z); p[3] = f2tf(pa[i].w);
        }
#pragma unroll
        for (int i = 0; i < 2; i++) {
            int id  = tid + i * 256;
            int row = id >> 5, cg = (id & 31) << 2;
            uint32_t* p = &Bs[buf][row * BSTR + cg];
            p[0] = f2tf(pb[i].x); p[1] = f2tf(pb[i].y);
            p[2] = f2tf(pb[i].z); p[3] = f2tf(pb[i].w);
        }
    };
    auto compute = [&](int buf) {
#pragma unroll
        for (int k8 = 0; k8 < 16; k8 += 8) {
            uint32_t af[4][4], bf[4][2];
#pragma unroll
            for (int mt = 0; mt < 4; mt++) {
                const uint32_t* p = &As[buf][(wm + mt * 16 + lq) * ASTR + k8 + lr];
                af[mt][0] = p[0];
                af[mt][1] = p[8 * ASTR];
                af[mt][2] = p[4];
                af[mt][3] = p[8 * ASTR + 4];
            }
#pragma unroll
            for (int nt = 0; nt < 4; nt++) {
                const uint32_t* p = &Bs[buf][(k8 + lr) * BSTR + wn + nt * 8 + lq];
                bf[nt][0] = p[0];
                bf[nt][1] = p[4 * BSTR];
            }
#pragma unroll
            for (int mt = 0; mt < 4; mt++)
#pragma unroll
                for (int nt = 0; nt < 4; nt++)
                    mma_tf32(acc[mt][nt], af[mt], bf[nt]);
        }
    };

    // ---- main loop: register-staged double buffering ----
    ldA(0); ldB(0);
    stAB(0);
    __syncthreads();
    for (int kt = 0; kt < nkt; kt++) {
        int buf = kt & 1;
        bool more = (kt + 1 < nkt);
        if (more) { ldA(kt + 1); ldB(kt + 1); }
        compute(buf);
        if (more) stAB(buf ^ 1);
        __syncthreads();
    }

    // ---- epilogue ----
#pragma unroll
    for (int mt = 0; mt < 4; mt++) {
        int rbase = br * 128 + wm + mt * 16 + lq;
#pragma unroll
        for (int nt = 0; nt < 4; nt++) {
            int col = bc * 128 + wn + nt * 8 + lr * 2;
            float b0 = bias[col], b1 = bias[col + 1];
#pragma unroll
            for (int hh = 0; hh < 2; hh++) {
                int row = rbase + hh * 8;
                int orow = mapGraph ? (row / NN) * L_ + NQ + (row % NN) : row;
                float v0 = acc[mt][nt][hh * 2 + 0] + b0;
                float v1 = acc[mt][nt][hh * 2 + 1] + b1;
                if (EPI == 1) {
                    v0 += resid[(size_t)row * N + col];
                    v1 += resid[(size_t)row * N + col + 1];
                }
                if (EPI == 2) {
                    v0 = 0.5f * v0 * (1.0f + erff(v0 * 0.7071067811865475f));
                    v1 = 0.5f * v1 * (1.0f + erff(v1 * 0.7071067811865475f));
                }
                float2 o = make_float2(v0, v1);
                *(float2*)(C + (size_t)orow * N + col) = o;
            }
        }
    }
}

// ============================================================================
// Row LayerNorm (D=768)
// ============================================================================
__global__ __launch_bounds__(256)
void ln_kernel(const float* __restrict__ in, float* __restrict__ out,
               const float* __restrict__ g, const float* __restrict__ bta,
               const float* __restrict__ pos, const float* __restrict__ tok)
{
    const int row = blockIdx.x;
    const int l = row % L_;
    const int tid = threadIdx.x;
    const float* ip = in + (size_t)row * D_;

    float v[3];
    float s = 0.f;
#pragma unroll
    for (int i = 0; i < 3; i++) {
        int d = tid + i * 256;
        float x = ip[d];
        if (pos) x += pos[l * D_ + d] + tok[d];
        v[i] = x;
        s += x;
    }
    __shared__ float red[256];
    red[tid] = s;
    __syncthreads();
    for (int o = 128; o > 0; o >>= 1) {
        if (tid < o) red[tid] += red[tid + o];
        __syncthreads();
    }
    float mean = red[0] * (1.0f / 768.0f);
    __syncthreads();

    float ss = 0.f;
#pragma unroll
    for (int i = 0; i < 3; i++) {
        float d0 = v[i] - mean;
        ss += d0 * d0;
    }
    red[tid] = ss;
    __syncthreads();
    for (int o = 128; o > 0; o >>= 1) {
        if (tid < o) red[tid] += red[tid + o];
        __syncthreads();
    }
    float inv = rsqrtf(red[0] * (1.0f / 768.0f) + 1e-12f);

    float* op = out + (size_t)row * D_;
#pragma unroll
    for (int i = 0; i < 3; i++) {
        int d = tid + i * 256;
        op[d] = (v[i] - mean) * inv * g[d] + bta[d];
    }
}

// ============================================================================
// Fused attention (fp32, unchanged from round 1)
// ============================================================================
constexpr int SW = 513;
constexpr int VW = 100;
constexpr int ATTN_SMEM =
    (96 * 64 * 2 + 64 * VW + 64 * SW) * 4 + L_ * 4;

__global__ __launch_bounds__(256)
void attn_kernel(const float* __restrict__ qkv, float* __restrict__ ctx,
                 const int* __restrict__ text_atts, const int* __restrict__ graph_mask)
{
    const int bh = blockIdx.x;
    const int b = bh / H_, h = bh % H_;
    const int qt = blockIdx.y;
    const int tid = threadIdx.x;

    extern __shared__ float sm[];
    float* Qs = sm;
    float* Ks = Qs + 96 * 64;
    float* Vs = Ks + 96 * 64;
    float* S  = Vs + 64 * VW;
    int*   keep = (int*)(S + 64 * SW);

    for (int j = tid; j < L_; j += 256)
        keep[j] = (j < NQ) ? 1
                : (j < TS) ? graph_mask[b * NN + (j - NQ)]
                           : text_atts[b * T_ + (j - TS)];

    const float* qbase = qkv + (size_t)(b * L_ + qt * 64) * (3 * D_) + h * HD;
    for (int e = tid; e < 64 * 24; e += 256) {
        int r = e / 24, c4 = (e % 24) * 4;
        float4 v = *(const float4*)(qbase + (size_t)r * (3 * D_) + c4);
        Qs[(c4 + 0) * 64 + r] = v.x;
        Qs[(c4 + 1) * 64 + r] = v.y;
        Qs[(c4 + 2) * 64 + r] = v.z;
        Qs[(c4 + 3) * 64 + r] = v.w;
    }
    __syncthreads();

    const int tx = tid & 15, ty = tid >> 4;
    const float scale = 0.10206207261596577f;

    for (int kc = 0; kc < 8; kc++) {
        const float* kb = qkv + (size_t)(b * L_ + kc * 64) * (3 * D_) + D_ + h * HD;
        for (int e = tid; e < 64 * 24; e += 256) {
            int r = e / 24, c4 = (e % 24) * 4;
            float4 v = *(const float4*)(kb + (size_t)r * (3 * D_) + c4);
            Ks[(c4 + 0) * 64 + r] = v.x;
            Ks[(c4 + 1) * 64 + r] = v.y;
            Ks[(c4 + 2) * 64 + r] = v.z;
            Ks[(c4 + 3) * 64 + r] = v.w;
        }
        __syncthreads();

        float acc[4][4];
#pragma unroll
        for (int i = 0; i < 4; i++)
#pragma unroll
            for (int j = 0; j < 4; j++) acc[i][j] = 0.f;

#pragma unroll 4
        for (int d = 0; d < 96; d++) {
            float a[4], bb[4];
#pragma unroll
            for (int i = 0; i < 4; i++) a[i]  = Qs[d * 64 + ty * 4 + i];
#pragma unroll
            for (int j = 0; j < 4; j++) bb[j] = Ks[d * 64 + tx * 4 + j];
#pragma unroll
            for (int i = 0; i < 4; i++)
#pragma unroll
                for (int j = 0; j < 4; j++) acc[i][j] += a[i] * bb[j];
        }

#pragma unroll
        for (int i = 0; i < 4; i++) {
            int qg = qt * 64 + ty * 4 + i;
            int kq = keep[qg];
#pragma unroll
            for (int j = 0; j < 4; j++) {
                int kg = kc * 64 + tx * 4 + j;
                bool ok = (kq != 0) && (keep[kg] != 0);
                if (qg < TS) {
                    if (kg >= TS) ok = false;
                } else if (kg >= TS) {
                    if (qg < kg) ok = false;
                }
                S[(ty * 4 + i) * SW + kg] = acc[i][j] * scale + (ok ? 0.f : NEGB);
            }
        }
        __syncthreads();
    }

    if (tid < 64) {
        float* row = S + tid * SW;
        float m = -INFINITY;
        for (int k = 0; k < L_; k++) m = fmaxf(m, row[k]);
        float sum = 0.f;
        for (int k = 0; k < L_; k++) {
            float e = __expf(row[k] - m);
            row[k] = e;
            sum += e;
        }
        float inv = 1.f / sum;
        for (int k = 0; k < L_; k++) row[k] *= inv;
    }
    __syncthreads();

    float o[4][6];
#pragma unroll
    for (int i = 0; i < 4; i++)
#pragma unroll
        for (int j = 0; j < 6; j++) o[i][j] = 0.f;

    for (int kc = 0; kc < 8; kc++) {
        const float* vb = qkv + (size_t)(b * L_ + kc * 64) * (3 * D_) + 2 * D_ + h * HD;
        for (int e = tid; e < 64 * 24; e += 256) {
            int r = e / 24, c4 = (e % 24) * 4;
            float4 v = *(const float4*)(vb + (size_t)r * (3 * D_) + c4);
            *(float4*)&Vs[r * VW + c4] = v;
        }
        __syncthreads();

#pragma unroll 2
        for (int ki = 0; ki < 64; ki++) {
            float a[4], bb[6];
#pragma unroll
            for (int i = 0; i < 4; i++) a[i] = S[(ty * 4 + i) * SW + kc * 64 + ki];
#pragma unroll
            for (int j = 0; j < 6; j++) bb[j] = Vs[ki * VW + tx * 6 + j];
#pragma unroll
            for (int i = 0; i < 4; i++)
#pragma unroll
                for (int j = 0; j < 6; j++) o[i][j] += a[i] * bb[j];
        }
        __syncthreads();
    }

#pragma unroll
    for (int i = 0; i < 4; i++) {
        float* op = ctx + (size_t)(b * L_ + qt * 64 + ty * 4 + i) * D_ + h * HD + tx * 6;
#pragma unroll
        for (int j = 0; j < 6; j++) op[j] = o[i][j];
    }
}

// ============================================================================
// misc elementwise
// ============================================================================
__global__ void fill_embed(const float* __restrict__ qtok,
                           const float* __restrict__ temb,
                           float* __restrict__ out)
{
    int idx = blockIdx.x * blockDim.x + threadIdx.x;
    if (idx >= B_ * L_ * D_) return;
    int rem = idx % (L_ * D_);
    int b = idx / (L_ * D_);
    int l = rem / D_, d = rem % D_;
    if (l < NQ)
        out[idx] = qtok[l * D_ + d];
    else if (l >= TS)
        out[idx] = temb[(size_t)(b * T_ + (l - TS)) * D_ + d];
}

__global__ void copy_out(const float* __restrict__ x, float* __restrict__ out, int n)
{
    int idx = blockIdx.x * blockDim.x + threadIdx.x;
    if (idx >= n) return;
    int rem = idx % (T_ * D_);
    int b = idx / (T_ * D_);
    int t = rem / D_, d = rem % D_;
    out[idx] = x[(size_t)(b * L_ + TS + t) * D_ + d];
}

// ============================================================================
// launcher
// ============================================================================
extern "C" void kernel_launch(void* const* d_in, const int* in_sizes, int n_in,
                              void* d_out, int out_size)
{
    const float* gnf     = (const float*)d_in[0];
    const float* temb    = (const float*)d_in[1];
    const int*   tatt    = (const int*)  d_in[2];
    const int*   gmask   = (const int*)  d_in[3];
    const float* qtok    = (const float*)d_in[4];
    const float* gproj_w = (const float*)d_in[5];
    const float* gproj_b = (const float*)d_in[6];
    const float* pos     = (const float*)d_in[7];
    const float* tok     = (const float*)d_in[8];
    const float* elng    = (const float*)d_in[9];
    const float* elnb    = (const float*)d_in[10];
    const float* qkvw    = (const float*)d_in[11];
    const float* qkvb    = (const float*)d_in[12];
    const float* aow     = (const float*)d_in[13];
    const float* aob     = (const float*)d_in[14];
    const float* ln1g    = (const float*)d_in[15];
    const float* ln1b    = (const float*)d_in[16];
    const float* ff1w    = (const float*)d_in[17];
    const float* ff1b    = (const float*)d_in[18];
    const float* ff2w    = (const float*)d_in[19];
    const float* ff2b    = (const float*)d_in[20];
    const float* ln2g    = (const float*)d_in[21];
    const float* ln2b    = (const float*)d_in[22];

    float *px, *ptmp, *pctx, *pqkv, *pff;
    cudaGetSymbolAddress((void**)&px,   g_x);
    cudaGetSymbolAddress((void**)&ptmp, g_tmp);
    cudaGetSymbolAddress((void**)&pctx, g_ctx);
    cudaGetSymbolAddress((void**)&pqkv, g_qkv);
    cudaGetSymbolAddress((void**)&pff,  g_ff);

    cudaFuncSetAttribute(attn_kernel, cudaFuncAttributeMaxDynamicSharedMemorySize,
                         ATTN_SMEM);

    const int NROWS = B_ * L_;   // 8192

    // ---- embeddings ----
    fill_embed<<<(B_ * L_ * D_ + 255) / 256, 256>>>(qtok, temb, ptmp);
    tgemm<0><<<dim3(D_ / 128, (B_ * NN) / 128), 256>>>(
        gnf, gproj_w, gproj_b, nullptr, ptmp, B_ * NN, D_, D_, 1);
    ln_kernel<<<NROWS, 256>>>(ptmp, px, elng, elnb, pos, tok);

    // ---- 6 encoder layers ----
    for (int i = 0; i < NLAY; i++) {
        tgemm<0><<<dim3((3 * D_) / 128, NROWS / 128), 256>>>(
            px, qkvw + (size_t)i * D_ * 3 * D_, qkvb + (size_t)i * 3 * D_,
            nullptr, pqkv, NROWS, 3 * D_, D_, 0);

        attn_kernel<<<dim3(B_ * H_, L_ / 64), 256, ATTN_SMEM>>>(pqkv, pctx, tatt, gmask);

        tgemm<1><<<dim3(D_ / 128, NROWS / 128), 256>>>(
            pctx, aow + (size_t)i * D_ * D_, aob + (size_t)i * D_,
            px, ptmp, NROWS, D_, D_, 0);
        ln_kernel<<<NROWS, 256>>>(ptmp, px, ln1g + (size_t)i * D_, ln1b + (size_t)i * D_,
                                  nullptr, nullptr);

        tgemm<2><<<dim3(FF / 128, NROWS / 128), 256>>>(
            px, ff1w + (size_t)i * D_ * FF, ff1b + (size_t)i * FF,
            nullptr, pff, NROWS, FF, D_, 0);

        tgemm<1><<<dim3(D_ / 128, NROWS / 128), 256>>>(
            pff, ff2w + (size_t)i * FF * D_, ff2b + (size_t)i * D_,
            px, ptmp, NROWS, D_, FF, 0);
        ln_kernel<<<NROWS, 256>>>(ptmp, px, ln2g + (size_t)i * D_, ln2b + (size_t)i * D_,
                                  nullptr, nullptr);
    }

    // ---- output: text rows ----
    copy_out<<<(out_size + 255) / 256, 256>>>(px, (float*)d_out, out_size);
}

// round 4
// speedup vs baseline: 2.6268x; 1.2722x over previous
#include <cuda_runtime.h>
#include <math.h>
#include <stdint.h>

// ---------------- problem dims ----------------
constexpr int B_   = 16;
constexpr int NQ   = 32;
constexpr int NN   = 128;
constexpr int T_   = 352;
constexpr int D_   = 768;
constexpr int H_   = 8;
constexpr int NLAY = 6;
constexpr int FF   = 3072;
constexpr int L_   = NQ + NN + T_;   // 512
constexpr int TS   = NQ + NN;        // 160 (text start)
constexpr int HD   = D_ / H_;        // 96
constexpr float NEGB = -1e9f;
constexpr int QKVS = 3 * D_;         // 2304

// ---------------- device scratch ----------------
__device__ float g_x  [B_ * L_ * D_];
__device__ float g_tmp[B_ * L_ * D_];
__device__ float g_ctx[B_ * L_ * D_];
__device__ float g_qkv[B_ * L_ * 3 * D_];
__device__ float g_ff [B_ * L_ * FF];

// ---------------- tf32 helpers ----------------
__device__ __forceinline__ uint32_t f2tf(float x) {
    uint32_t r;
    asm("cvt.rna.tf32.f32 %0, %1;" : "=r"(r) : "f"(x));
    return r;
}

__device__ __forceinline__ void mma_tf32(float c[4], const uint32_t a[4],
                                         const uint32_t b[2]) {
    asm volatile(
        "mma.sync.aligned.m16n8k8.row.col.f32.tf32.tf32.f32 "
        "{%0,%1,%2,%3}, {%4,%5,%6,%7}, {%8,%9}, {%0,%1,%2,%3};"
        : "+f"(c[0]), "+f"(c[1]), "+f"(c[2]), "+f"(c[3])
        : "r"(a[0]), "r"(a[1]), "r"(a[2]), "r"(a[3]), "r"(b[0]), "r"(b[1]));
}

// ============================================================================
// TF32 tensor-core GEMM (unchanged from round 2; 120 TF/s class)
// ============================================================================
constexpr int ASTR = 20;
constexpr int BSTR = 136;

template <int EPI>
__global__ __launch_bounds__(256)
void tgemm(const float* __restrict__ A, const float* __restrict__ Bm,
           const float* __restrict__ bias, const float* __restrict__ resid,
           float* __restrict__ C, int M, int N, int K, int mapGraph)
{
    __shared__ uint32_t As[2][128 * ASTR];
    __shared__ uint32_t Bs[2][16 * BSTR];

    const int tid  = threadIdx.x;
    const int br   = blockIdx.y, bc = blockIdx.x;
    const int lane = tid & 31,  wid = tid >> 5;
    const int wm = (wid >> 2) * 64;
    const int wn = (wid & 3) * 32;
    const int lq = lane >> 2;
    const int lr = lane & 3;

    float acc[4][4][4];
#pragma unroll
    for (int mt = 0; mt < 4; mt++)
#pragma unroll
        for (int nt = 0; nt < 4; nt++)
#pragma unroll
            for (int r = 0; r < 4; r++) acc[mt][nt][r] = 0.f;

    const int nkt = K >> 4;
    float4 pa[2], pb[2];

    auto ldA = [&](int kt) {
#pragma unroll
        for (int i = 0; i < 2; i++) {
            int id  = tid + i * 256;
            int row = id >> 2, cg = (id & 3) << 2;
            pa[i] = *(const float4*)(A + (size_t)(br * 128 + row) * K + kt * 16 + cg);
        }
    };
    auto ldB = [&](int kt) {
#pragma unroll
        for (int i = 0; i < 2; i++) {
            int id  = tid + i * 256;
            int row = id >> 5, cg = (id & 31) << 2;
            pb[i] = *(const float4*)(Bm + (size_t)(kt * 16 + row) * N + bc * 128 + cg);
        }
    };
    auto stAB = [&](int buf) {
#pragma unroll
        for (int i = 0; i < 2; i++) {
            int id  = tid + i * 256;
            int row = id >> 2, cg = (id & 3) << 2;
            uint32_t* p = &As[buf][row * ASTR + cg];
            p[0] = f2tf(pa[i].x); p[1] = f2tf(pa[i].y);
            p[2] = f2tf(pa[i].z); p[3] = f2tf(pa[i].w);
        }
#pragma unroll
        for (int i = 0; i < 2; i++) {
            int id  = tid + i * 256;
            int row = id >> 5, cg = (id & 31) << 2;
            uint32_t* p = &Bs[buf][row * BSTR + cg];
            p[0] = f2tf(pb[i].x); p[1] = f2tf(pb[i].y);
            p[2] = f2tf(pb[i].z); p[3] = f2tf(pb[i].w);
        }
    };
    auto compute = [&](int buf) {
#pragma unroll
        for (int k8 = 0; k8 < 16; k8 += 8) {
            uint32_t af[4][4], bf[4][2];
#pragma unroll
            for (int mt = 0; mt < 4; mt++) {
                const uint32_t* p = &As[buf][(wm + mt * 16 + lq) * ASTR + k8 + lr];
                af[mt][0] = p[0];
                af[mt][1] = p[8 * ASTR];
                af[mt][2] = p[4];
                af[mt][3] = p[8 * ASTR + 4];
            }
#pragma unroll
            for (int nt = 0; nt < 4; nt++) {
                const uint32_t* p = &Bs[buf][(k8 + lr) * BSTR + wn + nt * 8 + lq];
                bf[nt][0] = p[0];
                bf[nt][1] = p[4 * BSTR];
            }
#pragma unroll
            for (int mt = 0; mt < 4; mt++)
#pragma unroll
                for (int nt = 0; nt < 4; nt++)
                    mma_tf32(acc[mt][nt], af[mt], bf[nt]);
        }
    };

    ldA(0); ldB(0);
    stAB(0);
    __syncthreads();
    for (int kt = 0; kt < nkt; kt++) {
        int buf = kt & 1;
        bool more = (kt + 1 < nkt);
        if (more) { ldA(kt + 1); ldB(kt + 1); }
        compute(buf);
        if (more) stAB(buf ^ 1);
        __syncthreads();
    }

#pragma unroll
    for (int mt = 0; mt < 4; mt++) {
        int rbase = br * 128 + wm + mt * 16 + lq;
#pragma unroll
        for (int nt = 0; nt < 4; nt++) {
            int col = bc * 128 + wn + nt * 8 + lr * 2;
            float b0 = bias[col], b1 = bias[col + 1];
#pragma unroll
            for (int hh = 0; hh < 2; hh++) {
                int row = rbase + hh * 8;
                int orow = mapGraph ? (row / NN) * L_ + NQ + (row % NN) : row;
                float v0 = acc[mt][nt][hh * 2 + 0] + b0;
                float v1 = acc[mt][nt][hh * 2 + 1] + b1;
                if (EPI == 1) {
                    v0 += resid[(size_t)row * N + col];
                    v1 += resid[(size_t)row * N + col + 1];
                }
                if (EPI == 2) {
                    v0 = 0.5f * v0 * (1.0f + erff(v0 * 0.7071067811865475f));
                    v1 = 0.5f * v1 * (1.0f + erff(v1 * 0.7071067811865475f));
                }
                float2 o = make_float2(v0, v1);
                *(float2*)(C + (size_t)orow * N + col) = o;
            }
        }
    }
}

// ============================================================================
// Row LayerNorm (D=768)
// ============================================================================
__global__ __launch_bounds__(256)
void ln_kernel(const float* __restrict__ in, float* __restrict__ out,
               const float* __restrict__ g, const float* __restrict__ bta,
               const float* __restrict__ pos, const float* __restrict__ tok)
{
    const int row = blockIdx.x;
    const int l = row % L_;
    const int tid = threadIdx.x;
    const float* ip = in + (size_t)row * D_;

    float v[3];
    float s = 0.f;
#pragma unroll
    for (int i = 0; i < 3; i++) {
        int d = tid + i * 256;
        float x = ip[d];
        if (pos) x += pos[l * D_ + d] + tok[d];
        v[i] = x;
        s += x;
    }
    __shared__ float red[256];
    red[tid] = s;
    __syncthreads();
    for (int o = 128; o > 0; o >>= 1) {
        if (tid < o) red[tid] += red[tid + o];
        __syncthreads();
    }
    float mean = red[0] * (1.0f / 768.0f);
    __syncthreads();

    float ss = 0.f;
#pragma unroll
    for (int i = 0; i < 3; i++) {
        float d0 = v[i] - mean;
        ss += d0 * d0;
    }
    red[tid] = ss;
    __syncthreads();
    for (int o = 128; o > 0; o >>= 1) {
        if (tid < o) red[tid] += red[tid + o];
        __syncthreads();
    }
    float inv = rsqrtf(red[0] * (1.0f / 768.0f) + 1e-12f);

    float* op = out + (size_t)row * D_;
#pragma unroll
    for (int i = 0; i < 3; i++) {
        int d = tid + i * 256;
        op[d] = (v[i] - mean) * inv * g[d] + bta[d];
    }
}

// ============================================================================
// TF32 tensor-core attention. One block per (b*H+h, 64-query tile).
// smem tiles hold tf32; S holds fp32 scores then tf32 probabilities.
// Warp grid 4(m)x2(n): score warp tile 16x32, PV warp tile 16x48.
// ============================================================================
constexpr int KVW = 104;   // Q/K/V smem stride: 104 % 32 == 8 -> lane addr 8*lq+lr, conflict-free
constexpr int SW2 = 520;   // S stride: 520 % 32 == 8, same property
constexpr int ATTN_SMEM = (64 * KVW * 2 + 64 * SW2) * 4 + L_ * 4;

__global__ __launch_bounds__(256)
void attn_mma(const float* __restrict__ qkv, float* __restrict__ ctx,
              const int* __restrict__ text_atts, const int* __restrict__ graph_mask)
{
    const int bh = blockIdx.x;
    const int b = bh / H_, h = bh % H_;
    const int qt = blockIdx.y;
    const int tid = threadIdx.x;
    const int lane = tid & 31, wid = tid >> 5;
    const int lq = lane >> 2, lr = lane & 3;

    extern __shared__ uint32_t smu[];
    uint32_t* Qs = smu;                  // [64][KVW] tf32
    uint32_t* KV = Qs + 64 * KVW;        // [64][KVW] tf32 (K, then reused for V)
    uint32_t* Sb = KV + 64 * KVW;        // [64][SW2]
    int* keep = (int*)(Sb + 64 * SW2);   // [512]

    for (int j = tid; j < L_; j += 256)
        keep[j] = (j < NQ) ? 1
                : (j < TS) ? graph_mask[b * NN + (j - NQ)]
                           : text_atts[b * T_ + (j - TS)];

    // Q tile -> smem (tf32)
    const float* qbase = qkv + (size_t)(b * L_ + qt * 64) * QKVS + h * HD;
#pragma unroll
    for (int i = 0; i < 6; i++) {
        int e = tid + i * 256;
        int r = e / 24, c4 = (e % 24) * 4;
        float4 v = *(const float4*)(qbase + (size_t)r * QKVS + c4);
        uint32_t* p = &Qs[r * KVW + c4];
        p[0] = f2tf(v.x); p[1] = f2tf(v.y); p[2] = f2tf(v.z); p[3] = f2tf(v.w);
    }

    const int wm  = (wid >> 1) * 16;   // warp m base
    const int wnS = (wid & 1) * 32;    // score-phase warp n base
    const int wnV = (wid & 1) * 48;    // PV-phase warp n base
    const float scale = 0.10206207261596577f;   // 1/sqrt(96)

    float4 pre[6];
    auto ldKV = [&](int kc, int which) {   // which: 1=K, 2=V
        const float* base = qkv + (size_t)(b * L_ + kc * 64) * QKVS + which * D_ + h * HD;
#pragma unroll
        for (int i = 0; i < 6; i++) {
            int e = tid + i * 256;
            int r = e / 24, c4 = (e % 24) * 4;
            pre[i] = *(const float4*)(base + (size_t)r * QKVS + c4);
        }
    };
    auto stKV = [&]() {
#pragma unroll
        for (int i = 0; i < 6; i++) {
            int e = tid + i * 256;
            int r = e / 24, c4 = (e % 24) * 4;
            uint32_t* p = &KV[r * KVW + c4];
            p[0] = f2tf(pre[i].x); p[1] = f2tf(pre[i].y);
            p[2] = f2tf(pre[i].z); p[3] = f2tf(pre[i].w);
        }
    };

    // ---------------- score phase ----------------
    ldKV(0, 1);
    stKV();
    __syncthreads();          // also publishes Q + keep
    for (int kc = 0; kc < 8; kc++) {
        if (kc < 7) ldKV(kc + 1, 1);

        float sacc[4][4];
#pragma unroll
        for (int nt = 0; nt < 4; nt++)
#pragma unroll
            for (int r = 0; r < 4; r++) sacc[nt][r] = 0.f;

#pragma unroll
        for (int k8 = 0; k8 < 96; k8 += 8) {
            uint32_t af[4];
            const uint32_t* qp = &Qs[(wm + lq) * KVW + k8 + lr];
            af[0] = qp[0];
            af[1] = qp[8 * KVW];
            af[2] = qp[4];
            af[3] = qp[8 * KVW + 4];
#pragma unroll
            for (int nt = 0; nt < 4; nt++) {
                const uint32_t* kp = &KV[(wnS + nt * 8 + lq) * KVW + k8 + lr];
                uint32_t bf[2] = {kp[0], kp[4]};
                mma_tf32(sacc[nt], af, bf);
            }
        }

        float* Sf = (float*)Sb;
#pragma unroll
        for (int nt = 0; nt < 4; nt++) {
            int kg = kc * 64 + wnS + nt * 8 + 2 * lr;
            bool k0 = keep[kg] != 0, k1 = keep[kg + 1] != 0;
#pragma unroll
            for (int half = 0; half < 2; half++) {
                int qrow = wm + lq + half * 8;
                int qg = qt * 64 + qrow;
                bool qok = keep[qg] != 0;
                bool ok0 = qok && k0, ok1 = qok && k1;
                if (qg < TS) {                       // prefix cannot see text
                    if (kg     >= TS) ok0 = false;
                    if (kg + 1 >= TS) ok1 = false;
                } else {                             // text query: causal in text
                    if (kg     >= TS && qg < kg)     ok0 = false;
                    if (kg + 1 >= TS && qg < kg + 1) ok1 = false;
                }
                float v0 = sacc[nt][half * 2 + 0] * scale + (ok0 ? 0.f : NEGB);
                float v1 = sacc[nt][half * 2 + 1] * scale + (ok1 ? 0.f : NEGB);
                *(float2*)&Sf[qrow * SW2 + kg] = make_float2(v0, v1);
            }
        }
        __syncthreads();                // KV reads + S writes done
        if (kc < 7) { stKV(); __syncthreads(); }
    }

    // ---------------- softmax: 4 threads per row ----------------
    ldKV(0, 2);                         // prefetch V chunk 0 under softmax
    {
        int r = tid >> 2, p = tid & 3;
        float* row = (float*)Sb + r * SW2 + p * 128;
        float m = -INFINITY;
#pragma unroll 4
        for (int k = 0; k < 128; k++) m = fmaxf(m, row[k]);
        m = fmaxf(m, __shfl_xor_sync(0xffffffffu, m, 1));
        m = fmaxf(m, __shfl_xor_sync(0xffffffffu, m, 2));
        float sum = 0.f;
#pragma unroll 4
        for (int k = 0; k < 128; k++) {
            float e = __expf(row[k] - m);
            row[k] = e;
            sum += e;
        }
        sum += __shfl_xor_sync(0xffffffffu, sum, 1);
        sum += __shfl_xor_sync(0xffffffffu, sum, 2);
        float inv = 1.f / sum;
        uint32_t* rowb = Sb + r * SW2 + p * 128;
#pragma unroll 4
        for (int k = 0; k < 128; k++) rowb[k] = f2tf(row[k] * inv);
    }
    stKV();
    __syncthreads();

    // ---------------- P @ V phase ----------------
    float oacc[6][4];
#pragma unroll
    for (int nt = 0; nt < 6; nt++)
#pragma unroll
        for (int r = 0; r < 4; r++) oacc[nt][r] = 0.f;

    for (int kc = 0; kc < 8; kc++) {
        if (kc < 7) ldKV(kc + 1, 2);

#pragma unroll
        for (int k8 = 0; k8 < 64; k8 += 8) {
            uint32_t af[4];
            const uint32_t* pp = &Sb[(wm + lq) * SW2 + kc * 64 + k8 + lr];
            af[0] = pp[0];
            af[1] = pp[8 * SW2];
            af[2] = pp[4];
            af[3] = pp[8 * SW2 + 4];
#pragma unroll
            for (int nt = 0; nt < 6; nt++) {
                const uint32_t* vp = &KV[(k8 + lr) * KVW + wnV + nt * 8 + lq];
                uint32_t bf[2] = {vp[0], vp[4 * KVW]};
                mma_tf32(oacc[nt], af, bf);
            }
        }
        __syncthreads();
        if (kc < 7) { stKV(); __syncthreads(); }
    }

#pragma unroll
    for (int nt = 0; nt < 6; nt++) {
#pragma unroll
        for (int half = 0; half < 2; half++) {
            int qrow = qt * 64 + wm + lq + half * 8;
            int col = h * HD + wnV + nt * 8 + 2 * lr;
            float2 o = make_float2(oacc[nt][half * 2 + 0], oacc[nt][half * 2 + 1]);
            *(float2*)(ctx + (size_t)(b * L_ + qrow) * D_ + col) = o;
        }
    }
}

// ============================================================================
// misc elementwise
// ============================================================================
__global__ void fill_embed(const float* __restrict__ qtok,
                           const float* __restrict__ temb,
                           float* __restrict__ out)
{
    int idx = blockIdx.x * blockDim.x + threadIdx.x;
    if (idx >= B_ * L_ * D_) return;
    int rem = idx % (L_ * D_);
    int b = idx / (L_ * D_);
    int l = rem / D_, d = rem % D_;
    if (l < NQ)
        out[idx] = qtok[l * D_ + d];
    else if (l >= TS)
        out[idx] = temb[(size_t)(b * T_ + (l - TS)) * D_ + d];
}

__global__ void copy_out(const float* __restrict__ x, float* __restrict__ out, int n)
{
    int idx = blockIdx.x * blockDim.x + threadIdx.x;
    if (idx >= n) return;
    int rem = idx % (T_ * D_);
    int b = idx / (T_ * D_);
    int t = rem / D_, d = rem % D_;
    out[idx] = x[(size_t)(b * L_ + TS + t) * D_ + d];
}

// ============================================================================
// launcher
// ============================================================================
extern "C" void kernel_launch(void* const* d_in, const int* in_sizes, int n_in,
                              void* d_out, int out_size)
{
    const float* gnf     = (const float*)d_in[0];
    const float* temb    = (const float*)d_in[1];
    const int*   tatt    = (const int*)  d_in[2];
    const int*   gmask   = (const int*)  d_in[3];
    const float* qtok    = (const float*)d_in[4];
    const float* gproj_w = (const float*)d_in[5];
    const float* gproj_b = (const float*)d_in[6];
    const float* pos     = (const float*)d_in[7];
    const float* tok     = (const float*)d_in[8];
    const float* elng    = (const float*)d_in[9];
    const float* elnb    = (const float*)d_in[10];
    const float* qkvw    = (const float*)d_in[11];
    const float* qkvb    = (const float*)d_in[12];
    const float* aow     = (const float*)d_in[13];
    const float* aob     = (const float*)d_in[14];
    const float* ln1g    = (const float*)d_in[15];
    const float* ln1b    = (const float*)d_in[16];
    const float* ff1w    = (const float*)d_in[17];
    const float* ff1b    = (const float*)d_in[18];
    const float* ff2w    = (const float*)d_in[19];
    const float* ff2b    = (const float*)d_in[20];
    const float* ln2g    = (const float*)d_in[21];
    const float* ln2b    = (const float*)d_in[22];

    float *px, *ptmp, *pctx, *pqkv, *pff;
    cudaGetSymbolAddress((void**)&px,   g_x);
    cudaGetSymbolAddress((void**)&ptmp, g_tmp);
    cudaGetSymbolAddress((void**)&pctx, g_ctx);
    cudaGetSymbolAddress((void**)&pqkv, g_qkv);
    cudaGetSymbolAddress((void**)&pff,  g_ff);

    cudaFuncSetAttribute(attn_mma, cudaFuncAttributeMaxDynamicSharedMemorySize,
                         ATTN_SMEM);

    const int NROWS = B_ * L_;   // 8192

    // ---- embeddings ----
    fill_embed<<<(B_ * L_ * D_ + 255) / 256, 256>>>(qtok, temb, ptmp);
    tgemm<0><<<dim3(D_ / 128, (B_ * NN) / 128), 256>>>(
        gnf, gproj_w, gproj_b, nullptr, ptmp, B_ * NN, D_, D_, 1);
    ln_kernel<<<NROWS, 256>>>(ptmp, px, elng, elnb, pos, tok);

    // ---- 6 encoder layers ----
    for (int i = 0; i < NLAY; i++) {
        tgemm<0><<<dim3((3 * D_) / 128, NROWS / 128), 256>>>(
            px, qkvw + (size_t)i * D_ * 3 * D_, qkvb + (size_t)i * 3 * D_,
            nullptr, pqkv, NROWS, 3 * D_, D_, 0);

        attn_mma<<<dim3(B_ * H_, L_ / 64), 256, ATTN_SMEM>>>(pqkv, pctx, tatt, gmask);

        tgemm<1><<<dim3(D_ / 128, NROWS / 128), 256>>>(
            pctx, aow + (size_t)i * D_ * D_, aob + (size_t)i * D_,
            px, ptmp, NROWS, D_, D_, 0);
        ln_kernel<<<NROWS, 256>>>(ptmp, px, ln1g + (size_t)i * D_, ln1b + (size_t)i * D_,
                                  nullptr, nullptr);

        tgemm<2><<<dim3(FF / 128, NROWS / 128), 256>>>(
            px, ff1w + (size_t)i * D_ * FF, ff1b + (size_t)i * FF,
            nullptr, pff, NROWS, FF, D_, 0);

        tgemm<1><<<dim3(D_ / 128, NROWS / 128), 256>>>(
            pff, ff2w + (size_t)i * FF * D_, ff2b + (size_t)i * D_,
            px, ptmp, NROWS, D_, FF, 0);
        ln_kernel<<<NROWS, 256>>>(ptmp, px, ln2g + (size_t)i * D_, ln2b + (size_t)i * D_,
                                  nullptr, nullptr);
    }

    // ---- output: text rows ----
    copy_out<<<(out_size + 255) / 256, 256>>>(px, (float*)d_out, out_size);
}